// round 12
// baseline (speedup 1.0000x reference)
#include <cuda_runtime.h>
#include <cuda_fp16.h>
#include <cstdint>

// Problem constants (fixed by reference)
#define BWIN   2048
#define NTOK   49
#define CDIM   384
#define HHEADS 12
#define DH     32
#define NWMASK 64
#define THREEC 1152
#define MROWS  (BWIN * NTOK)   // 100352

// Scratch (allocation-free rule: __device__ globals)
__device__ __half g_qkvh[(size_t)MROWS * THREEC];   // qkv, fp16 (QKV GEMM out)
__device__ __half g_atth[(size_t)MROWS * CDIM];     // attention out, fp16

// ---------------------------------------------------------------------------
// helpers
// ---------------------------------------------------------------------------
__device__ __forceinline__ void mma_f16_k16(float c[4],
                                            uint32_t a0, uint32_t a1, uint32_t a2, uint32_t a3,
                                            uint32_t b0, uint32_t b1) {
    asm volatile(
        "mma.sync.aligned.m16n8k16.row.col.f32.f16.f16.f32 "
        "{%0,%1,%2,%3}, {%4,%5,%6,%7}, {%8,%9}, {%0,%1,%2,%3};"
        : "+f"(c[0]), "+f"(c[1]), "+f"(c[2]), "+f"(c[3])
        : "r"(a0), "r"(a1), "r"(a2), "r"(a3), "r"(b0), "r"(b1));
}

__device__ __forceinline__ void mma_f16_k8(float c[4],
                                           uint32_t a0, uint32_t a1, uint32_t b0) {
    asm volatile(
        "mma.sync.aligned.m16n8k8.row.col.f32.f16.f16.f32 "
        "{%0,%1,%2,%3}, {%4,%5}, {%6}, {%0,%1,%2,%3};"
        : "+f"(c[0]), "+f"(c[1]), "+f"(c[2]), "+f"(c[3])
        : "r"(a0), "r"(a1), "r"(b0));
}

__device__ __forceinline__ void ldsm4(uint32_t& r0, uint32_t& r1,
                                      uint32_t& r2, uint32_t& r3, uint32_t addr) {
    asm volatile("ldmatrix.sync.aligned.m8n8.x4.shared.b16 {%0,%1,%2,%3}, [%4];"
                 : "=r"(r0), "=r"(r1), "=r"(r2), "=r"(r3) : "r"(addr));
}

__device__ __forceinline__ uint32_t smem_u32(const void* p) {
    return (uint32_t)__cvta_generic_to_shared(p);
}

// load one 8-element chunk as 8 fp16 packed in uint4, converting if needed
__device__ __forceinline__ uint4 ld_chunk(const __half* p) {
    return *(const uint4*)p;
}
__device__ __forceinline__ uint4 ld_chunk(const float* p) {
    const float4 lo = *(const float4*)p;
    const float4 hi = *(const float4*)(p + 4);
    const __half2 h0 = __floats2half2_rn(lo.x, lo.y);
    const __half2 h1 = __floats2half2_rn(lo.z, lo.w);
    const __half2 h2 = __floats2half2_rn(hi.x, hi.y);
    const __half2 h3 = __floats2half2_rn(hi.z, hi.w);
    uint4 u;
    u.x = *(const uint32_t*)&h0;
    u.y = *(const uint32_t*)&h1;
    u.z = *(const uint32_t*)&h2;
    u.w = *(const uint32_t*)&h3;
    return u;
}

// ---------------------------------------------------------------------------
// fp16 tensor-core GEMM v8: v7 structure + fused input conversion
// C = A @ W^T + bias, fp32 accum. A: [M,K] (TA), W: [Nout,K] (TW).
// CTA tile 256x128, 256 threads = 8 warps (4m x 2n), warp tile 64x64,
// stage BK=64 (two 32-wide producer phases), ONE __syncthreads per stage.
// Fragment-permuted smem, dense per 64-wide stage (A 8192 w, B 4096 w).
// ---------------------------------------------------------------------------
#define AWORDS 8192
#define BWORDS 4096
#define GEMM_SMEM ((AWORDS + BWORDS) * 2 * 4)   // 98304

template <typename TA, typename TW, typename TO>
__global__ __launch_bounds__(256, 1) void gemm_f16_v8(
    const TA* __restrict__ A,
    const TW* __restrict__ W,
    const float* __restrict__ bias,
    TO* __restrict__ C,
    int Nout, int K)
{
    extern __shared__ __align__(16) uint32_t dsm[];
    uint32_t* const As = dsm;                     // [2][AWORDS]
    uint32_t* const Bs = dsm + 2 * AWORDS;        // [2][BWORDS]

    const int tid  = threadIdx.x;
    const int bm   = blockIdx.y * 256;
    const int bn   = blockIdx.x * 128;
    const int lane = tid & 31;
    const int warp = tid >> 5;
    const int warp_m = warp >> 1;    // 0..3 (64-row slab)
    const int warp_n = warp & 1;     // 0..1 (64-col slab)
    const int g = lane >> 2;
    const int t = lane & 3;

    const int ldr = tid >> 2;            // 0..63
    const int c   = tid & 3;             // 0..3
    const int kks0 = c >> 1;
    const int ph   = c & 1;

    const TA* Ab = A + (size_t)(bm + ldr) * K + c * 8;
    const TW* Wb = W + (size_t)(bn + ldr) * K + c * 8;

    int aoff[2][4], boff[2][2];
#pragma unroll
    for (int p = 0; p < 2; ++p) {
        const int kks = kks0 + p * 2;
#pragma unroll
        for (int i = 0; i < 4; ++i) {
            const int row = ldr + i * 64;
            const int mi  = row >> 4;
            const int lr  = row & 15;
            aoff[p][i] = ((kks * 16 + mi) * 4 + ((lr >> 3) + 2 * ph)) * 32 + (lr & 7) * 4;
        }
#pragma unroll
        for (int i = 0; i < 2; ++i) {
            const int n = ldr + i * 64;
            boff[p][i] = ((kks * 16 + (n >> 3)) * 2 + ph) * 32 + (n & 7) * 4;
        }
    }

    uint4 ar[4], wr[2];

    auto load_ph = [&](int s, int p) {
        const int k0 = s * 64 + p * 32;
        ar[0] = ld_chunk(Ab + k0);
        ar[1] = ld_chunk(Ab + (size_t)64  * K + k0);
        ar[2] = ld_chunk(Ab + (size_t)128 * K + k0);
        ar[3] = ld_chunk(Ab + (size_t)192 * K + k0);
        wr[0] = ld_chunk(Wb + k0);
        wr[1] = ld_chunk(Wb + (size_t)64  * K + k0);
    };
    auto stash_ph = [&](int bf, int p) {
        uint32_t* Ad = As + bf * AWORDS;
        uint32_t* Bd = Bs + bf * BWORDS;
#pragma unroll
        for (int i = 0; i < 4; ++i) *(uint4*)&Ad[aoff[p][i]] = ar[i];
#pragma unroll
        for (int i = 0; i < 2; ++i) *(uint4*)&Bd[boff[p][i]] = wr[i];
    };

    float acc[4][8][4] = {};
    auto mma_step = [&](int bf, int kk) {
        uint32_t af[4][4], bfr[8][2];
        const uint32_t* Ap = As + bf * AWORDS + ((kk * 16 + warp_m * 4) * 4) * 32 + lane;
        const uint32_t* Bp = Bs + bf * BWORDS + ((kk * 16 + warp_n * 8) * 2) * 32 + lane;
#pragma unroll
        for (int mi = 0; mi < 4; ++mi)
#pragma unroll
            for (int r = 0; r < 4; ++r)
                af[mi][r] = Ap[(mi * 4 + r) * 32];
#pragma unroll
        for (int ni = 0; ni < 8; ++ni) {
            bfr[ni][0] = Bp[ni * 64];
            bfr[ni][1] = Bp[ni * 64 + 32];
        }
#pragma unroll
        for (int mi = 0; mi < 4; ++mi)
#pragma unroll
            for (int ni = 0; ni < 8; ++ni)
                mma_f16_k16(acc[mi][ni],
                            af[mi][0], af[mi][1], af[mi][2], af[mi][3],
                            bfr[ni][0], bfr[ni][1]);
    };

    load_ph(0, 0); stash_ph(0, 0);
    load_ph(0, 1); stash_ph(0, 1);
    __syncthreads();

    const int NS = K / 64;   // 6
    int buf = 0;
    for (int s = 0; s < NS; ++s) {
        const bool more = (s + 1 < NS);
        if (more) load_ph(s + 1, 0);
        mma_step(buf, 0);
        mma_step(buf, 1);
        if (more) { stash_ph(buf ^ 1, 0); load_ph(s + 1, 1); }
        mma_step(buf, 2);
        mma_step(buf, 3);
        if (more) {
            stash_ph(buf ^ 1, 1);
            __syncthreads();
            buf ^= 1;
        }
    }

    // epilogue: frag layout m16n8: c0=(g,2t) c1=(g,2t+1) c2=(g+8,2t) c3=(g+8,2t+1)
#pragma unroll
    for (int mi = 0; mi < 4; ++mi) {
#pragma unroll
        for (int ni = 0; ni < 8; ++ni) {
            const int row = bm + warp_m * 64 + mi * 16 + g;
            const int col = bn + warp_n * 64 + ni * 8 + 2 * t;
            const float b0v = __ldg(bias + col);
            const float b1v = __ldg(bias + col + 1);
            const float v00 = acc[mi][ni][0] + b0v, v01 = acc[mi][ni][1] + b1v;
            const float v10 = acc[mi][ni][2] + b0v, v11 = acc[mi][ni][3] + b1v;
            if constexpr (sizeof(TO) == 2) {
                *(__half2*)((__half*)C + (size_t)row * Nout + col) =
                    __floats2half2_rn(v00, v01);
                *(__half2*)((__half*)C + (size_t)(row + 8) * Nout + col) =
                    __floats2half2_rn(v10, v11);
            } else {
                *(float2*)((float*)C + (size_t)row * Nout + col) = make_float2(v00, v01);
                *(float2*)((float*)C + (size_t)(row + 8) * Nout + col) = make_float2(v10, v11);
            }
        }
    }
}

// ---------------------------------------------------------------------------
// Tensor-core attention: one CTA (128 threads, 4 warps) per (window b, head h).
// (unchanged — measured ~130 us, rel_err-verified)
// ---------------------------------------------------------------------------
__global__ __launch_bounds__(128) void attn_mma(const float* __restrict__ mask)
{
    const int b = blockIdx.x;
    const int h = blockIdx.y;
    const int tid  = threadIdx.x;
    const int lane = tid & 31;
    const int w    = tid >> 5;
    const int g = lane >> 2;
    const int t = lane & 3;

    __shared__ __align__(16) __half qh[64][40];
    __shared__ __align__(16) __half kh[64][40];
    __shared__ __align__(16) __half vt[32][72];

    for (int i = tid; i < 64 * 20; i += 128) {
        ((uint32_t*)qh)[i] = 0;
        ((uint32_t*)kh)[i] = 0;
    }
    for (int i = tid; i < 32 * 36; i += 128) ((uint32_t*)vt)[i] = 0;
    __syncthreads();

    const __half* base = g_qkvh + (size_t)(b * NTOK) * THREEC + h * DH;
    for (int idx = tid; idx < NTOK * 16; idx += 128) {
        const int n  = idx >> 4;
        const int d2 = idx & 15;
        const uint32_t* p = (const uint32_t*)(base + (size_t)n * THREEC) + d2;
        const uint32_t q = p[0];
        const uint32_t k = p[CDIM / 2];
        const uint32_t v = p[CDIM];
        *(uint32_t*)&qh[n][d2 * 2] = q;
        *(uint32_t*)&kh[n][d2 * 2] = k;
        const __half2 vh = *(const __half2*)&v;
        vt[d2 * 2][n]     = __low2half(vh);
        vt[d2 * 2 + 1][n] = __high2half(vh);
    }
    __syncthreads();

    const int m0 = w * 16;
    const int r   = lane & 7;
    const int mat = lane >> 3;
    const int lrow = r + (mat & 1) * 8;
    const int lcol = (mat >> 1) * 8;

    uint32_t a[2][4];
#pragma unroll
    for (int s = 0; s < 2; ++s)
        ldsm4(a[s][0], a[s][1], a[s][2], a[s][3],
              smem_u32(&qh[m0 + lrow][lcol + s * 16]));

    float c[7][4] = {};
#pragma unroll
    for (int s = 0; s < 2; ++s) {
#pragma unroll
        for (int p = 0; p < 4; ++p) {
            uint32_t b0, b1, b2, b3;
            ldsm4(b0, b1, b2, b3, smem_u32(&kh[16 * p + lrow][lcol + s * 16]));
            mma_f16_k16(c[2 * p], a[s][0], a[s][1], a[s][2], a[s][3], b0, b2);
            if (2 * p + 1 < 7)
                mma_f16_k16(c[2 * p + 1], a[s][0], a[s][1], a[s][2], a[s][3], b1, b3);
        }
    }

    const float scale = 0.17677669529663687f;
    const float* mrow = mask + (size_t)(b & (NWMASK - 1)) * NTOK * NTOK;
    const int i1 = m0 + g;
    const int i2 = m0 + 8 + g;
    const int mi1 = (i1 < NTOK) ? i1 : NTOK - 1;
    const int mi2 = (i2 < NTOK) ? i2 : NTOK - 1;
#pragma unroll
    for (int nt = 0; nt < 7; ++nt) {
        const int j0 = nt * 8 + 2 * t;
        c[nt][0] = (j0     < NTOK) ? c[nt][0] * scale + __ldg(mrow + mi1 * NTOK + j0)     : -1e30f;
        c[nt][1] = (j0 + 1 < NTOK) ? c[nt][1] * scale + __ldg(mrow + mi1 * NTOK + j0 + 1) : -1e30f;
        c[nt][2] = (j0     < NTOK) ? c[nt][2] * scale + __ldg(mrow + mi2 * NTOK + j0)     : -1e30f;
        c[nt][3] = (j0 + 1 < NTOK) ? c[nt][3] * scale + __ldg(mrow + mi2 * NTOK + j0 + 1) : -1e30f;
    }

    float mx1 = -1e30f, mx2 = -1e30f;
#pragma unroll
    for (int nt = 0; nt < 7; ++nt) {
        mx1 = fmaxf(mx1, fmaxf(c[nt][0], c[nt][1]));
        mx2 = fmaxf(mx2, fmaxf(c[nt][2], c[nt][3]));
    }
    mx1 = fmaxf(mx1, __shfl_xor_sync(0xffffffffu, mx1, 1));
    mx1 = fmaxf(mx1, __shfl_xor_sync(0xffffffffu, mx1, 2));
    mx2 = fmaxf(mx2, __shfl_xor_sync(0xffffffffu, mx2, 1));
    mx2 = fmaxf(mx2, __shfl_xor_sync(0xffffffffu, mx2, 2));

    float s1 = 0.f, s2 = 0.f;
#pragma unroll
    for (int nt = 0; nt < 7; ++nt) {
        c[nt][0] = __expf(c[nt][0] - mx1);
        c[nt][1] = __expf(c[nt][1] - mx1);
        c[nt][2] = __expf(c[nt][2] - mx2);
        c[nt][3] = __expf(c[nt][3] - mx2);
        s1 += c[nt][0] + c[nt][1];
        s2 += c[nt][2] + c[nt][3];
    }
    s1 += __shfl_xor_sync(0xffffffffu, s1, 1);
    s1 += __shfl_xor_sync(0xffffffffu, s1, 2);
    s2 += __shfl_xor_sync(0xffffffffu, s2, 1);
    s2 += __shfl_xor_sync(0xffffffffu, s2, 2);
    const float inv1 = 1.0f / s1;
    const float inv2 = 1.0f / s2;

    uint32_t pa[7][2];
#pragma unroll
    for (int nt = 0; nt < 7; ++nt) {
        const __half2 p0 = __floats2half2_rn(c[nt][0] * inv1, c[nt][1] * inv1);
        const __half2 p1 = __floats2half2_rn(c[nt][2] * inv2, c[nt][3] * inv2);
        pa[nt][0] = *(const uint32_t*)&p0;
        pa[nt][1] = *(const uint32_t*)&p1;
    }

    float o[4][4] = {};
#pragma unroll
    for (int kc = 0; kc < 7; ++kc) {
#pragma unroll
        for (int dt = 0; dt < 4; ++dt) {
            const uint32_t bv = *(const uint32_t*)&vt[dt * 8 + g][kc * 8 + 2 * t];
            mma_f16_k8(o[dt], pa[kc][0], pa[kc][1], bv);
        }
    }

    __half* ob = g_atth + (size_t)(b * NTOK) * CDIM + h * DH;
#pragma unroll
    for (int dt = 0; dt < 4; ++dt) {
        const int d0 = dt * 8 + 2 * t;
        if (i1 < NTOK)
            *(__half2*)(ob + (size_t)i1 * CDIM + d0) = __floats2half2_rn(o[dt][0], o[dt][1]);
        if (i2 < NTOK)
            *(__half2*)(ob + (size_t)i2 * CDIM + d0) = __floats2half2_rn(o[dt][2], o[dt][3]);
    }
}

// ---------------------------------------------------------------------------
// launch — no prepass kernels; conversions fused into GEMM producers
// ---------------------------------------------------------------------------
extern "C" void kernel_launch(void* const* d_in, const int* in_sizes, int n_in,
                              void* d_out, int out_size)
{
    const float* x      = (const float*)d_in[0];
    const float* mask   = (const float*)d_in[1];
    const float* qkv_w  = (const float*)d_in[2];
    const float* qkv_b  = (const float*)d_in[3];
    const float* proj_w = (const float*)d_in[4];
    const float* proj_b = (const float*)d_in[5];
    float* out = (float*)d_out;

    __half *qkvh_ptr, *atth_ptr;
    cudaGetSymbolAddress((void**)&qkvh_ptr, g_qkvh);
    cudaGetSymbolAddress((void**)&atth_ptr, g_atth);

    cudaFuncSetAttribute((const void*)gemm_f16_v8<float, float, __half>,
                         cudaFuncAttributeMaxDynamicSharedMemorySize, GEMM_SMEM);
    cudaFuncSetAttribute((const void*)gemm_f16_v8<__half, float, float>,
                         cudaFuncAttributeMaxDynamicSharedMemorySize, GEMM_SMEM);

    // 1) QKV GEMM: fp32 in (fused cvt) / fp16 out
    {
        dim3 grid(THREEC / 128, MROWS / 256);   // (9, 392)
        gemm_f16_v8<float, float, __half><<<grid, 256, GEMM_SMEM>>>(
            x, qkv_w, qkv_b, qkvh_ptr, THREEC, CDIM);
    }
    // 2) windowed attention (tensor cores, fp16 in/out)
    {
        dim3 grid(BWIN, HHEADS);
        attn_mma<<<grid, 128>>>(mask);
    }
    // 3) Proj GEMM: fp16 A / fp32 W (fused cvt) / fp32 out
    {
        dim3 grid(CDIM / 128, MROWS / 256);     // (3, 392)
        gemm_f16_v8<__half, float, float><<<grid, 256, GEMM_SMEM>>>(
            atth_ptr, proj_w, proj_b, out, CDIM, CDIM);
    }
}

// round 13
// speedup vs baseline: 1.0366x; 1.0366x over previous
#include <cuda_runtime.h>
#include <cuda_fp16.h>
#include <cstdint>

// Problem constants (fixed by reference)
#define BWIN   2048
#define NTOK   49
#define CDIM   384
#define HHEADS 12
#define DH     32
#define NWMASK 64
#define THREEC 1152
#define MROWS  (BWIN * NTOK)   // 100352

// Scratch (allocation-free rule: __device__ globals)
__device__ __half g_qkvh[(size_t)MROWS * THREEC];   // qkv, fp16
__device__ __half g_xh  [(size_t)MROWS * CDIM];     // x, fp16
__device__ __half g_atth[(size_t)MROWS * CDIM];     // attention out, fp16
__device__ __half g_wqh [(size_t)THREEC * CDIM];    // qkv_w, fp16
__device__ __half g_wph [(size_t)CDIM * CDIM];      // proj_w, fp16

// ---------------------------------------------------------------------------
// helpers
// ---------------------------------------------------------------------------
__device__ __forceinline__ void mma_f16_k16(float c[4],
                                            uint32_t a0, uint32_t a1, uint32_t a2, uint32_t a3,
                                            uint32_t b0, uint32_t b1) {
    asm volatile(
        "mma.sync.aligned.m16n8k16.row.col.f32.f16.f16.f32 "
        "{%0,%1,%2,%3}, {%4,%5,%6,%7}, {%8,%9}, {%0,%1,%2,%3};"
        : "+f"(c[0]), "+f"(c[1]), "+f"(c[2]), "+f"(c[3])
        : "r"(a0), "r"(a1), "r"(a2), "r"(a3), "r"(b0), "r"(b1));
}

__device__ __forceinline__ void mma_f16_k8(float c[4],
                                           uint32_t a0, uint32_t a1, uint32_t b0) {
    asm volatile(
        "mma.sync.aligned.m16n8k8.row.col.f32.f16.f16.f32 "
        "{%0,%1,%2,%3}, {%4,%5}, {%6}, {%0,%1,%2,%3};"
        : "+f"(c[0]), "+f"(c[1]), "+f"(c[2]), "+f"(c[3])
        : "r"(a0), "r"(a1), "r"(b0));
}

__device__ __forceinline__ void ldsm4(uint32_t& r0, uint32_t& r1,
                                      uint32_t& r2, uint32_t& r3, uint32_t addr) {
    asm volatile("ldmatrix.sync.aligned.m8n8.x4.shared.b16 {%0,%1,%2,%3}, [%4];"
                 : "=r"(r0), "=r"(r1), "=r"(r2), "=r"(r3) : "r"(addr));
}

__device__ __forceinline__ uint32_t smem_u32(const void* p) {
    return (uint32_t)__cvta_generic_to_shared(p);
}

// ---------------------------------------------------------------------------
// fused prepass: one launch converts x, qkv_w, proj_w (fp32 -> fp16, rn)
// region boundaries in units of 8 floats
// ---------------------------------------------------------------------------
#define N8_X  ((MROWS * CDIM) / 8)      // 602112
#define N8_WQ ((THREEC * CDIM) / 8)     // 55296
#define N8_WP ((CDIM * CDIM) / 8)       // 18432
#define N8_TOT (N8_X + N8_WQ + N8_WP)

__global__ void prepass_kernel(const float* __restrict__ x,
                               const float* __restrict__ wq,
                               const float* __restrict__ wp)
{
    __half *xh, *wqh, *wph;
    const int i = blockIdx.x * blockDim.x + threadIdx.x;
    if (i >= N8_TOT) return;

    const float* src;
    __half* dst;
    int j;
    if (i < N8_X)               { src = x;  dst = g_xh;  j = i; }
    else if (i < N8_X + N8_WQ)  { src = wq; dst = g_wqh; j = i - N8_X; }
    else                        { src = wp; dst = g_wph; j = i - N8_X - N8_WQ; }

    const float4 v0 = ((const float4*)src)[2 * j];
    const float4 v1 = ((const float4*)src)[2 * j + 1];
    __half2 h[4];
    h[0] = __floats2half2_rn(v0.x, v0.y);
    h[1] = __floats2half2_rn(v0.z, v0.w);
    h[2] = __floats2half2_rn(v1.x, v1.y);
    h[3] = __floats2half2_rn(v1.z, v1.w);
    ((uint4*)dst)[j] = *(uint4*)h;
}

// ---------------------------------------------------------------------------
// fp16 tensor-core GEMM v7 (R11 verbatim — proven 424 us QKV):
// CTA tile 256x128, 256 threads = 8 warps (4m x 2n), warp tile 64x64.
// Stage BK=64, two 32-wide producer phases, ONE __syncthreads per stage.
// ---------------------------------------------------------------------------
#define AWORDS 8192
#define BWORDS 4096
#define GEMM_SMEM ((AWORDS + BWORDS) * 2 * 4)   // 98304

template <typename TO>
__global__ __launch_bounds__(256, 1) void gemm_f16_v7(
    const __half* __restrict__ A,
    const __half* __restrict__ W,
    const float* __restrict__ bias,
    TO* __restrict__ C,
    int Nout, int K)
{
    extern __shared__ __align__(16) uint32_t dsm[];
    uint32_t* const As = dsm;                     // [2][AWORDS]
    uint32_t* const Bs = dsm + 2 * AWORDS;        // [2][BWORDS]

    const int tid  = threadIdx.x;
    const int bm   = blockIdx.y * 256;
    const int bn   = blockIdx.x * 128;
    const int lane = tid & 31;
    const int warp = tid >> 5;
    const int warp_m = warp >> 1;
    const int warp_n = warp & 1;
    const int g = lane >> 2;
    const int t = lane & 3;

    const int ldr = tid >> 2;
    const int c   = tid & 3;
    const int kks0 = c >> 1;
    const int ph   = c & 1;

    const __half* Ab = A + (size_t)(bm + ldr) * K + c * 8;
    const __half* Wb = W + (size_t)(bn + ldr) * K + c * 8;

    int aoff[2][4], boff[2][2];
#pragma unroll
    for (int p = 0; p < 2; ++p) {
        const int kks = kks0 + p * 2;
#pragma unroll
        for (int i = 0; i < 4; ++i) {
            const int row = ldr + i * 64;
            const int mi  = row >> 4;
            const int lr  = row & 15;
            aoff[p][i] = ((kks * 16 + mi) * 4 + ((lr >> 3) + 2 * ph)) * 32 + (lr & 7) * 4;
        }
#pragma unroll
        for (int i = 0; i < 2; ++i) {
            const int n = ldr + i * 64;
            boff[p][i] = ((kks * 16 + (n >> 3)) * 2 + ph) * 32 + (n & 7) * 4;
        }
    }

    uint4 ar[4], wr[2];

    auto load_ph = [&](int s, int p) {
        const int k0 = s * 64 + p * 32;
        ar[0] = *(const uint4*)(Ab + k0);
        ar[1] = *(const uint4*)(Ab + (size_t)64  * K + k0);
        ar[2] = *(const uint4*)(Ab + (size_t)128 * K + k0);
        ar[3] = *(const uint4*)(Ab + (size_t)192 * K + k0);
        wr[0] = *(const uint4*)(Wb + k0);
        wr[1] = *(const uint4*)(Wb + (size_t)64  * K + k0);
    };
    auto stash_ph = [&](int bf, int p) {
        uint32_t* Ad = As + bf * AWORDS;
        uint32_t* Bd = Bs + bf * BWORDS;
#pragma unroll
        for (int i = 0; i < 4; ++i) *(uint4*)&Ad[aoff[p][i]] = ar[i];
#pragma unroll
        for (int i = 0; i < 2; ++i) *(uint4*)&Bd[boff[p][i]] = wr[i];
    };

    float acc[4][8][4] = {};
    auto mma_step = [&](int bf, int kk) {
        uint32_t af[4][4], bfr[8][2];
        const uint32_t* Ap = As + bf * AWORDS + ((kk * 16 + warp_m * 4) * 4) * 32 + lane;
        const uint32_t* Bp = Bs + bf * BWORDS + ((kk * 16 + warp_n * 8) * 2) * 32 + lane;
#pragma unroll
        for (int mi = 0; mi < 4; ++mi)
#pragma unroll
            for (int r = 0; r < 4; ++r)
                af[mi][r] = Ap[(mi * 4 + r) * 32];
#pragma unroll
        for (int ni = 0; ni < 8; ++ni) {
            bfr[ni][0] = Bp[ni * 64];
            bfr[ni][1] = Bp[ni * 64 + 32];
        }
#pragma unroll
        for (int mi = 0; mi < 4; ++mi)
#pragma unroll
            for (int ni = 0; ni < 8; ++ni)
                mma_f16_k16(acc[mi][ni],
                            af[mi][0], af[mi][1], af[mi][2], af[mi][3],
                            bfr[ni][0], bfr[ni][1]);
    };

    load_ph(0, 0); stash_ph(0, 0);
    load_ph(0, 1); stash_ph(0, 1);
    __syncthreads();

    const int NS = K / 64;   // 6
    int buf = 0;
    for (int s = 0; s < NS; ++s) {
        const bool more = (s + 1 < NS);
        if (more) load_ph(s + 1, 0);
        mma_step(buf, 0);
        mma_step(buf, 1);
        if (more) { stash_ph(buf ^ 1, 0); load_ph(s + 1, 1); }
        mma_step(buf, 2);
        mma_step(buf, 3);
        if (more) {
            stash_ph(buf ^ 1, 1);
            __syncthreads();
            buf ^= 1;
        }
    }

#pragma unroll
    for (int mi = 0; mi < 4; ++mi) {
#pragma unroll
        for (int ni = 0; ni < 8; ++ni) {
            const int row = bm + warp_m * 64 + mi * 16 + g;
            const int col = bn + warp_n * 64 + ni * 8 + 2 * t;
            const float b0v = __ldg(bias + col);
            const float b1v = __ldg(bias + col + 1);
            const float v00 = acc[mi][ni][0] + b0v, v01 = acc[mi][ni][1] + b1v;
            const float v10 = acc[mi][ni][2] + b0v, v11 = acc[mi][ni][3] + b1v;
            if constexpr (sizeof(TO) == 2) {
                *(__half2*)((__half*)C + (size_t)row * Nout + col) =
                    __floats2half2_rn(v00, v01);
                *(__half2*)((__half*)C + (size_t)(row + 8) * Nout + col) =
                    __floats2half2_rn(v10, v11);
            } else {
                *(float2*)((float*)C + (size_t)row * Nout + col) = make_float2(v00, v01);
                *(float2*)((float*)C + (size_t)(row + 8) * Nout + col) = make_float2(v10, v11);
            }
        }
    }
}

// ---------------------------------------------------------------------------
// Tensor-core attention: one CTA (128 threads, 4 warps) per (window b, head h).
// R7 structure + mask staged in smem (coalesced gmem loads, conflict-free LDS).
// ---------------------------------------------------------------------------
__global__ __launch_bounds__(128) void attn_mma(const float* __restrict__ mask)
{
    const int b = blockIdx.x;
    const int h = blockIdx.y;
    const int tid  = threadIdx.x;
    const int lane = tid & 31;
    const int w    = tid >> 5;
    const int g = lane >> 2;
    const int t = lane & 3;

    __shared__ __align__(16) __half qh[64][40];
    __shared__ __align__(16) __half kh[64][40];
    __shared__ __align__(16) __half vt[32][72];
    __shared__ float msk[NTOK][53];   // 53: conflict-free for (row=g-based, col=2t-based)

    for (int i = tid; i < 64 * 20; i += 128) {
        ((uint32_t*)qh)[i] = 0;
        ((uint32_t*)kh)[i] = 0;
    }
    for (int i = tid; i < 32 * 36; i += 128) ((uint32_t*)vt)[i] = 0;
    __syncthreads();

    // stage qkv + mask
    const __half* base = g_qkvh + (size_t)(b * NTOK) * THREEC + h * DH;
    for (int idx = tid; idx < NTOK * 16; idx += 128) {
        const int n  = idx >> 4;
        const int d2 = idx & 15;
        const uint32_t* p = (const uint32_t*)(base + (size_t)n * THREEC) + d2;
        const uint32_t q = p[0];
        const uint32_t k = p[CDIM / 2];
        const uint32_t v = p[CDIM];
        *(uint32_t*)&qh[n][d2 * 2] = q;
        *(uint32_t*)&kh[n][d2 * 2] = k;
        const __half2 vh = *(const __half2*)&v;
        vt[d2 * 2][n]     = __low2half(vh);
        vt[d2 * 2 + 1][n] = __high2half(vh);
    }
    {
        const float* mrow = mask + (size_t)(b & (NWMASK - 1)) * NTOK * NTOK;
        for (int i = tid; i < NTOK * NTOK; i += 128)
            msk[i / NTOK][i - (i / NTOK) * NTOK] = mrow[i];
    }
    __syncthreads();

    const int m0 = w * 16;
    const int r   = lane & 7;
    const int mat = lane >> 3;
    const int lrow = r + (mat & 1) * 8;
    const int lcol = (mat >> 1) * 8;

    uint32_t a[2][4];
#pragma unroll
    for (int s = 0; s < 2; ++s)
        ldsm4(a[s][0], a[s][1], a[s][2], a[s][3],
              smem_u32(&qh[m0 + lrow][lcol + s * 16]));

    float c[7][4] = {};
#pragma unroll
    for (int s = 0; s < 2; ++s) {
#pragma unroll
        for (int p = 0; p < 4; ++p) {
            uint32_t b0, b1, b2, b3;
            ldsm4(b0, b1, b2, b3, smem_u32(&kh[16 * p + lrow][lcol + s * 16]));
            mma_f16_k16(c[2 * p], a[s][0], a[s][1], a[s][2], a[s][3], b0, b2);
            if (2 * p + 1 < 7)
                mma_f16_k16(c[2 * p + 1], a[s][0], a[s][1], a[s][2], a[s][3], b1, b3);
        }
    }

    const float scale = 0.17677669529663687f;
    const int i1 = m0 + g;
    const int i2 = m0 + 8 + g;
    const int mi1 = (i1 < NTOK) ? i1 : NTOK - 1;
    const int mi2 = (i2 < NTOK) ? i2 : NTOK - 1;
#pragma unroll
    for (int nt = 0; nt < 7; ++nt) {
        const int j0 = nt * 8 + 2 * t;
        c[nt][0] = (j0     < NTOK) ? c[nt][0] * scale + msk[mi1][j0]     : -1e30f;
        c[nt][1] = (j0 + 1 < NTOK) ? c[nt][1] * scale + msk[mi1][j0 + 1] : -1e30f;
        c[nt][2] = (j0     < NTOK) ? c[nt][2] * scale + msk[mi2][j0]     : -1e30f;
        c[nt][3] = (j0 + 1 < NTOK) ? c[nt][3] * scale + msk[mi2][j0 + 1] : -1e30f;
    }

    float mx1 = -1e30f, mx2 = -1e30f;
#pragma unroll
    for (int nt = 0; nt < 7; ++nt) {
        mx1 = fmaxf(mx1, fmaxf(c[nt][0], c[nt][1]));
        mx2 = fmaxf(mx2, fmaxf(c[nt][2], c[nt][3]));
    }
    mx1 = fmaxf(mx1, __shfl_xor_sync(0xffffffffu, mx1, 1));
    mx1 = fmaxf(mx1, __shfl_xor_sync(0xffffffffu, mx1, 2));
    mx2 = fmaxf(mx2, __shfl_xor_sync(0xffffffffu, mx2, 1));
    mx2 = fmaxf(mx2, __shfl_xor_sync(0xffffffffu, mx2, 2));

    float s1 = 0.f, s2 = 0.f;
#pragma unroll
    for (int nt = 0; nt < 7; ++nt) {
        c[nt][0] = __expf(c[nt][0] - mx1);
        c[nt][1] = __expf(c[nt][1] - mx1);
        c[nt][2] = __expf(c[nt][2] - mx2);
        c[nt][3] = __expf(c[nt][3] - mx2);
        s1 += c[nt][0] + c[nt][1];
        s2 += c[nt][2] + c[nt][3];
    }
    s1 += __shfl_xor_sync(0xffffffffu, s1, 1);
    s1 += __shfl_xor_sync(0xffffffffu, s1, 2);
    s2 += __shfl_xor_sync(0xffffffffu, s2, 1);
    s2 += __shfl_xor_sync(0xffffffffu, s2, 2);
    const float inv1 = 1.0f / s1;
    const float inv2 = 1.0f / s2;

    uint32_t pa[7][2];
#pragma unroll
    for (int nt = 0; nt < 7; ++nt) {
        const __half2 p0 = __floats2half2_rn(c[nt][0] * inv1, c[nt][1] * inv1);
        const __half2 p1 = __floats2half2_rn(c[nt][2] * inv2, c[nt][3] * inv2);
        pa[nt][0] = *(const uint32_t*)&p0;
        pa[nt][1] = *(const uint32_t*)&p1;
    }

    float o[4][4] = {};
#pragma unroll
    for (int kc = 0; kc < 7; ++kc) {
#pragma unroll
        for (int dt = 0; dt < 4; ++dt) {
            const uint32_t bv = *(const uint32_t*)&vt[dt * 8 + g][kc * 8 + 2 * t];
            mma_f16_k8(o[dt], pa[kc][0], pa[kc][1], bv);
        }
    }

    __half* ob = g_atth + (size_t)(b * NTOK) * CDIM + h * DH;
#pragma unroll
    for (int dt = 0; dt < 4; ++dt) {
        const int d0 = dt * 8 + 2 * t;
        if (i1 < NTOK)
            *(__half2*)(ob + (size_t)i1 * CDIM + d0) = __floats2half2_rn(o[dt][0], o[dt][1]);
        if (i2 < NTOK)
            *(__half2*)(ob + (size_t)i2 * CDIM + d0) = __floats2half2_rn(o[dt][2], o[dt][3]);
    }
}

// ---------------------------------------------------------------------------
// launch
// ---------------------------------------------------------------------------
extern "C" void kernel_launch(void* const* d_in, const int* in_sizes, int n_in,
                              void* d_out, int out_size)
{
    const float* x      = (const float*)d_in[0];
    const float* mask   = (const float*)d_in[1];
    const float* qkv_w  = (const float*)d_in[2];
    const float* qkv_b  = (const float*)d_in[3];
    const float* proj_w = (const float*)d_in[4];
    const float* proj_b = (const float*)d_in[5];
    float* out = (float*)d_out;

    __half *qkvh_ptr, *xh_ptr, *atth_ptr, *wqh_ptr, *wph_ptr;
    cudaGetSymbolAddress((void**)&qkvh_ptr, g_qkvh);
    cudaGetSymbolAddress((void**)&xh_ptr,   g_xh);
    cudaGetSymbolAddress((void**)&atth_ptr, g_atth);
    cudaGetSymbolAddress((void**)&wqh_ptr,  g_wqh);
    cudaGetSymbolAddress((void**)&wph_ptr,  g_wph);

    cudaFuncSetAttribute(gemm_f16_v7<__half>,
                         cudaFuncAttributeMaxDynamicSharedMemorySize, GEMM_SMEM);
    cudaFuncSetAttribute(gemm_f16_v7<float>,
                         cudaFuncAttributeMaxDynamicSharedMemorySize, GEMM_SMEM);

    // 0) fused fp32 -> fp16 prepass (single launch)
    prepass_kernel<<<(N8_TOT + 255) / 256, 256>>>(x, qkv_w, proj_w);

    // 1) QKV GEMM: fp16 in / fp16 out
    {
        dim3 grid(THREEC / 128, MROWS / 256);   // (9, 392)
        gemm_f16_v7<__half><<<grid, 256, GEMM_SMEM>>>(xh_ptr, wqh_ptr, qkv_b,
                                                      qkvh_ptr, THREEC, CDIM);
    }
    // 2) windowed attention (tensor cores, fp16 in/out)
    {
        dim3 grid(BWIN, HHEADS);
        attn_mma<<<grid, 128>>>(mask);
    }
    // 3) Proj GEMM: fp16 in / fp32 out
    {
        dim3 grid(CDIM / 128, MROWS / 256);     // (3, 392)
        gemm_f16_v7<float><<<grid, 256, GEMM_SMEM>>>(atth_ptr, wph_ptr, proj_b,
                                                     out, CDIM, CDIM);
    }
}

// round 15
// speedup vs baseline: 1.1212x; 1.0816x over previous
#include <cuda_runtime.h>
#include <cuda_fp16.h>
#include <cstdint>

// Problem constants (fixed by reference)
#define BWIN   2048
#define NTOK   49
#define CDIM   384
#define HHEADS 12
#define DH     32
#define NWMASK 64
#define THREEC 1152
#define MROWS  (BWIN * NTOK)   // 100352

// Scratch (allocation-free rule: __device__ globals)
__device__ __half g_qkvh[(size_t)MROWS * THREEC];   // qkv, fp16
__device__ __half g_xh  [(size_t)MROWS * CDIM];     // x, fp16
__device__ __half g_atth[(size_t)MROWS * CDIM];     // attention out, fp16
__device__ __half g_wqh [(size_t)THREEC * CDIM];    // qkv_w, fp16
__device__ __half g_wph [(size_t)CDIM * CDIM];      // proj_w, fp16

// ---------------------------------------------------------------------------
// helpers
// ---------------------------------------------------------------------------
__device__ __forceinline__ void mma_f16_k16(float c[4],
                                            uint32_t a0, uint32_t a1, uint32_t a2, uint32_t a3,
                                            uint32_t b0, uint32_t b1) {
    asm volatile(
        "mma.sync.aligned.m16n8k16.row.col.f32.f16.f16.f32 "
        "{%0,%1,%2,%3}, {%4,%5,%6,%7}, {%8,%9}, {%0,%1,%2,%3};"
        : "+f"(c[0]), "+f"(c[1]), "+f"(c[2]), "+f"(c[3])
        : "r"(a0), "r"(a1), "r"(a2), "r"(a3), "r"(b0), "r"(b1));
}

__device__ __forceinline__ void mma_f16_k8(float c[4],
                                           uint32_t a0, uint32_t a1, uint32_t b0) {
    asm volatile(
        "mma.sync.aligned.m16n8k8.row.col.f32.f16.f16.f32 "
        "{%0,%1,%2,%3}, {%4,%5}, {%6}, {%0,%1,%2,%3};"
        : "+f"(c[0]), "+f"(c[1]), "+f"(c[2]), "+f"(c[3])
        : "r"(a0), "r"(a1), "r"(b0));
}

__device__ __forceinline__ void ldsm4(uint32_t& r0, uint32_t& r1,
                                      uint32_t& r2, uint32_t& r3, uint32_t addr) {
    asm volatile("ldmatrix.sync.aligned.m8n8.x4.shared.b16 {%0,%1,%2,%3}, [%4];"
                 : "=r"(r0), "=r"(r1), "=r"(r2), "=r"(r3) : "r"(addr));
}

__device__ __forceinline__ uint32_t smem_u32(const void* p) {
    return (uint32_t)__cvta_generic_to_shared(p);
}

// ---------------------------------------------------------------------------
// fused prepass: one launch converts x, qkv_w, proj_w (fp32 -> fp16, rn)
// ---------------------------------------------------------------------------
#define N8_X  ((MROWS * CDIM) / 8)      // 602112
#define N8_WQ ((THREEC * CDIM) / 8)     // 55296
#define N8_WP ((CDIM * CDIM) / 8)       // 18432
#define N8_TOT (N8_X + N8_WQ + N8_WP)

__global__ void prepass_kernel(const float* __restrict__ x,
                               const float* __restrict__ wq,
                               const float* __restrict__ wp)
{
    const int i = blockIdx.x * blockDim.x + threadIdx.x;
    if (i >= N8_TOT) return;

    const float* src;
    __half* dst;
    int j;
    if (i < N8_X)               { src = x;  dst = g_xh;  j = i; }
    else if (i < N8_X + N8_WQ)  { src = wq; dst = g_wqh; j = i - N8_X; }
    else                        { src = wp; dst = g_wph; j = i - N8_X - N8_WQ; }

    const float4 v0 = ((const float4*)src)[2 * j];
    const float4 v1 = ((const float4*)src)[2 * j + 1];
    __half2 h[4];
    h[0] = __floats2half2_rn(v0.x, v0.y);
    h[1] = __floats2half2_rn(v0.z, v0.w);
    h[2] = __floats2half2_rn(v1.x, v1.y);
    h[3] = __floats2half2_rn(v1.z, v1.w);
    ((uint4*)dst)[j] = *(uint4*)h;
}

// ---------------------------------------------------------------------------
// fp16 tensor-core GEMM v7 (R11 verbatim — proven 424 us QKV / 148 us proj):
// CTA tile 256x128, 256 threads = 8 warps (4m x 2n), warp tile 64x64.
// Stage BK=64, two 32-wide producer phases, ONE __syncthreads per stage.
// ---------------------------------------------------------------------------
#define AWORDS 8192
#define BWORDS 4096
#define GEMM_SMEM ((AWORDS + BWORDS) * 2 * 4)   // 98304

template <typename TO>
__global__ __launch_bounds__(256, 1) void gemm_f16_v7(
    const __half* __restrict__ A,
    const __half* __restrict__ W,
    const float* __restrict__ bias,
    TO* __restrict__ C,
    int Nout, int K)
{
    extern __shared__ __align__(16) uint32_t dsm[];
    uint32_t* const As = dsm;                     // [2][AWORDS]
    uint32_t* const Bs = dsm + 2 * AWORDS;        // [2][BWORDS]

    const int tid  = threadIdx.x;
    const int bm   = blockIdx.y * 256;
    const int bn   = blockIdx.x * 128;
    const int lane = tid & 31;
    const int warp = tid >> 5;
    const int warp_m = warp >> 1;
    const int warp_n = warp & 1;
    const int g = lane >> 2;
    const int t = lane & 3;

    const int ldr = tid >> 2;
    const int c   = tid & 3;
    const int kks0 = c >> 1;
    const int ph   = c & 1;

    const __half* Ab = A + (size_t)(bm + ldr) * K + c * 8;
    const __half* Wb = W + (size_t)(bn + ldr) * K + c * 8;

    int aoff[2][4], boff[2][2];
#pragma unroll
    for (int p = 0; p < 2; ++p) {
        const int kks = kks0 + p * 2;
#pragma unroll
        for (int i = 0; i < 4; ++i) {
            const int row = ldr + i * 64;
            const int mi  = row >> 4;
            const int lr  = row & 15;
            aoff[p][i] = ((kks * 16 + mi) * 4 + ((lr >> 3) + 2 * ph)) * 32 + (lr & 7) * 4;
        }
#pragma unroll
        for (int i = 0; i < 2; ++i) {
            const int n = ldr + i * 64;
            boff[p][i] = ((kks * 16 + (n >> 3)) * 2 + ph) * 32 + (n & 7) * 4;
        }
    }

    uint4 ar[4], wr[2];

    auto load_ph = [&](int s, int p) {
        const int k0 = s * 64 + p * 32;
        ar[0] = *(const uint4*)(Ab + k0);
        ar[1] = *(const uint4*)(Ab + (size_t)64  * K + k0);
        ar[2] = *(const uint4*)(Ab + (size_t)128 * K + k0);
        ar[3] = *(const uint4*)(Ab + (size_t)192 * K + k0);
        wr[0] = *(const uint4*)(Wb + k0);
        wr[1] = *(const uint4*)(Wb + (size_t)64  * K + k0);
    };
    auto stash_ph = [&](int bf, int p) {
        uint32_t* Ad = As + bf * AWORDS;
        uint32_t* Bd = Bs + bf * BWORDS;
#pragma unroll
        for (int i = 0; i < 4; ++i) *(uint4*)&Ad[aoff[p][i]] = ar[i];
#pragma unroll
        for (int i = 0; i < 2; ++i) *(uint4*)&Bd[boff[p][i]] = wr[i];
    };

    float acc[4][8][4] = {};
    auto mma_step = [&](int bf, int kk) {
        uint32_t af[4][4], bfr[8][2];
        const uint32_t* Ap = As + bf * AWORDS + ((kk * 16 + warp_m * 4) * 4) * 32 + lane;
        const uint32_t* Bp = Bs + bf * BWORDS + ((kk * 16 + warp_n * 8) * 2) * 32 + lane;
#pragma unroll
        for (int mi = 0; mi < 4; ++mi)
#pragma unroll
            for (int r = 0; r < 4; ++r)
                af[mi][r] = Ap[(mi * 4 + r) * 32];
#pragma unroll
        for (int ni = 0; ni < 8; ++ni) {
            bfr[ni][0] = Bp[ni * 64];
            bfr[ni][1] = Bp[ni * 64 + 32];
        }
#pragma unroll
        for (int mi = 0; mi < 4; ++mi)
#pragma unroll
            for (int ni = 0; ni < 8; ++ni)
                mma_f16_k16(acc[mi][ni],
                            af[mi][0], af[mi][1], af[mi][2], af[mi][3],
                            bfr[ni][0], bfr[ni][1]);
    };

    load_ph(0, 0); stash_ph(0, 0);
    load_ph(0, 1); stash_ph(0, 1);
    __syncthreads();

    const int NS = K / 64;   // 6
    int buf = 0;
    for (int s = 0; s < NS; ++s) {
        const bool more = (s + 1 < NS);
        if (more) load_ph(s + 1, 0);
        mma_step(buf, 0);
        mma_step(buf, 1);
        if (more) { stash_ph(buf ^ 1, 0); load_ph(s + 1, 1); }
        mma_step(buf, 2);
        mma_step(buf, 3);
        if (more) {
            stash_ph(buf ^ 1, 1);
            __syncthreads();
            buf ^= 1;
        }
    }

#pragma unroll
    for (int mi = 0; mi < 4; ++mi) {
#pragma unroll
        for (int ni = 0; ni < 8; ++ni) {
            const int row = bm + warp_m * 64 + mi * 16 + g;
            const int col = bn + warp_n * 64 + ni * 8 + 2 * t;
            const float b0v = __ldg(bias + col);
            const float b1v = __ldg(bias + col + 1);
            const float v00 = acc[mi][ni][0] + b0v, v01 = acc[mi][ni][1] + b1v;
            const float v10 = acc[mi][ni][2] + b0v, v11 = acc[mi][ni][3] + b1v;
            if constexpr (sizeof(TO) == 2) {
                *(__half2*)((__half*)C + (size_t)row * Nout + col) =
                    __floats2half2_rn(v00, v01);
                *(__half2*)((__half*)C + (size_t)(row + 8) * Nout + col) =
                    __floats2half2_rn(v10, v11);
            } else {
                *(float2*)((float*)C + (size_t)row * Nout + col) = make_float2(v00, v01);
                *(float2*)((float*)C + (size_t)(row + 8) * Nout + col) = make_float2(v10, v11);
            }
        }
    }
}

// ---------------------------------------------------------------------------
// Tensor-core attention: one CTA (128 threads, 4 warps) per (window b, head h).
// R11 data path (__ldg mask, 14.7KB smem). vt-only zero-init, now with the
// REQUIRED __syncthreads between the zero loop and the data-store loop
// (R14's miss: without it another thread's zero can clobber written V data).
// qh/kh garbage is safe: invalid-j c-entries are unconditionally REPLACED by
// -1e30; invalid-i rows are per-row-independent in softmax and store-guarded.
// ---------------------------------------------------------------------------
__global__ __launch_bounds__(128) void attn_mma(const float* __restrict__ mask)
{
    const int b = blockIdx.x;
    const int h = blockIdx.y;
    const int tid  = threadIdx.x;
    const int lane = tid & 31;
    const int w    = tid >> 5;
    const int g = lane >> 2;
    const int t = lane & 3;

    __shared__ __align__(16) __half qh[64][40];
    __shared__ __align__(16) __half kh[64][40];
    __shared__ __align__(16) __half vt[32][72];

    // zero-init vt (9 words per thread), then BARRIER before data writes
    for (int i = tid; i < 32 * 36; i += 128) ((uint32_t*)vt)[i] = 0;
    __syncthreads();

    const __half* base = g_qkvh + (size_t)(b * NTOK) * THREEC + h * DH;
    for (int idx = tid; idx < NTOK * 16; idx += 128) {
        const int n  = idx >> 4;
        const int d2 = idx & 15;
        const uint32_t* p = (const uint32_t*)(base + (size_t)n * THREEC) + d2;
        const uint32_t q = p[0];
        const uint32_t k = p[CDIM / 2];
        const uint32_t v = p[CDIM];
        *(uint32_t*)&qh[n][d2 * 2] = q;
        *(uint32_t*)&kh[n][d2 * 2] = k;
        const __half2 vh = *(const __half2*)&v;
        vt[d2 * 2][n]     = __low2half(vh);
        vt[d2 * 2 + 1][n] = __high2half(vh);
    }
    __syncthreads();

    const int m0 = w * 16;
    const int r   = lane & 7;
    const int mat = lane >> 3;
    const int lrow = r + (mat & 1) * 8;
    const int lcol = (mat >> 1) * 8;

    uint32_t a[2][4];
#pragma unroll
    for (int s = 0; s < 2; ++s)
        ldsm4(a[s][0], a[s][1], a[s][2], a[s][3],
              smem_u32(&qh[m0 + lrow][lcol + s * 16]));

    float c[7][4] = {};
#pragma unroll
    for (int s = 0; s < 2; ++s) {
#pragma unroll
        for (int p = 0; p < 4; ++p) {
            uint32_t b0, b1, b2, b3;
            ldsm4(b0, b1, b2, b3, smem_u32(&kh[16 * p + lrow][lcol + s * 16]));
            mma_f16_k16(c[2 * p], a[s][0], a[s][1], a[s][2], a[s][3], b0, b2);
            if (2 * p + 1 < 7)
                mma_f16_k16(c[2 * p + 1], a[s][0], a[s][1], a[s][2], a[s][3], b1, b3);
        }
    }

    const float scale = 0.17677669529663687f;
    const float* mrow = mask + (size_t)(b & (NWMASK - 1)) * NTOK * NTOK;
    const int i1 = m0 + g;
    const int i2 = m0 + 8 + g;
    const int mi1 = (i1 < NTOK) ? i1 : NTOK - 1;
    const int mi2 = (i2 < NTOK) ? i2 : NTOK - 1;
#pragma unroll
    for (int nt = 0; nt < 7; ++nt) {
        const int j0 = nt * 8 + 2 * t;
        c[nt][0] = (j0     < NTOK) ? c[nt][0] * scale + __ldg(mrow + mi1 * NTOK + j0)     : -1e30f;
        c[nt][1] = (j0 + 1 < NTOK) ? c[nt][1] * scale + __ldg(mrow + mi1 * NTOK + j0 + 1) : -1e30f;
        c[nt][2] = (j0     < NTOK) ? c[nt][2] * scale + __ldg(mrow + mi2 * NTOK + j0)     : -1e30f;
        c[nt][3] = (j0 + 1 < NTOK) ? c[nt][3] * scale + __ldg(mrow + mi2 * NTOK + j0 + 1) : -1e30f;
    }

    float mx1 = -1e30f, mx2 = -1e30f;
#pragma unroll
    for (int nt = 0; nt < 7; ++nt) {
        mx1 = fmaxf(mx1, fmaxf(c[nt][0], c[nt][1]));
        mx2 = fmaxf(mx2, fmaxf(c[nt][2], c[nt][3]));
    }
    mx1 = fmaxf(mx1, __shfl_xor_sync(0xffffffffu, mx1, 1));
    mx1 = fmaxf(mx1, __shfl_xor_sync(0xffffffffu, mx1, 2));
    mx2 = fmaxf(mx2, __shfl_xor_sync(0xffffffffu, mx2, 1));
    mx2 = fmaxf(mx2, __shfl_xor_sync(0xffffffffu, mx2, 2));

    float s1 = 0.f, s2 = 0.f;
#pragma unroll
    for (int nt = 0; nt < 7; ++nt) {
        c[nt][0] = __expf(c[nt][0] - mx1);
        c[nt][1] = __expf(c[nt][1] - mx1);
        c[nt][2] = __expf(c[nt][2] - mx2);
        c[nt][3] = __expf(c[nt][3] - mx2);
        s1 += c[nt][0] + c[nt][1];
        s2 += c[nt][2] + c[nt][3];
    }
    s1 += __shfl_xor_sync(0xffffffffu, s1, 1);
    s1 += __shfl_xor_sync(0xffffffffu, s1, 2);
    s2 += __shfl_xor_sync(0xffffffffu, s2, 1);
    s2 += __shfl_xor_sync(0xffffffffu, s2, 2);
    const float inv1 = 1.0f / s1;
    const float inv2 = 1.0f / s2;

    uint32_t pa[7][2];
#pragma unroll
    for (int nt = 0; nt < 7; ++nt) {
        const __half2 p0 = __floats2half2_rn(c[nt][0] * inv1, c[nt][1] * inv1);
        const __half2 p1 = __floats2half2_rn(c[nt][2] * inv2, c[nt][3] * inv2);
        pa[nt][0] = *(const uint32_t*)&p0;
        pa[nt][1] = *(const uint32_t*)&p1;
    }

    float o[4][4] = {};
#pragma unroll
    for (int kc = 0; kc < 7; ++kc) {
#pragma unroll
        for (int dt = 0; dt < 4; ++dt) {
            const uint32_t bv = *(const uint32_t*)&vt[dt * 8 + g][kc * 8 + 2 * t];
            mma_f16_k8(o[dt], pa[kc][0], pa[kc][1], bv);
        }
    }

    __half* ob = g_atth + (size_t)(b * NTOK) * CDIM + h * DH;
#pragma unroll
    for (int dt = 0; dt < 4; ++dt) {
        const int d0 = dt * 8 + 2 * t;
        if (i1 < NTOK)
            *(__half2*)(ob + (size_t)i1 * CDIM + d0) = __floats2half2_rn(o[dt][0], o[dt][1]);
        if (i2 < NTOK)
            *(__half2*)(ob + (size_t)i2 * CDIM + d0) = __floats2half2_rn(o[dt][2], o[dt][3]);
    }
}

// ---------------------------------------------------------------------------
// launch
// ---------------------------------------------------------------------------
extern "C" void kernel_launch(void* const* d_in, const int* in_sizes, int n_in,
                              void* d_out, int out_size)
{
    const float* x      = (const float*)d_in[0];
    const float* mask   = (const float*)d_in[1];
    const float* qkv_w  = (const float*)d_in[2];
    const float* qkv_b  = (const float*)d_in[3];
    const float* proj_w = (const float*)d_in[4];
    const float* proj_b = (const float*)d_in[5];
    float* out = (float*)d_out;

    __half *qkvh_ptr, *xh_ptr, *atth_ptr, *wqh_ptr, *wph_ptr;
    cudaGetSymbolAddress((void**)&qkvh_ptr, g_qkvh);
    cudaGetSymbolAddress((void**)&xh_ptr,   g_xh);
    cudaGetSymbolAddress((void**)&atth_ptr, g_atth);
    cudaGetSymbolAddress((void**)&wqh_ptr,  g_wqh);
    cudaGetSymbolAddress((void**)&wph_ptr,  g_wph);

    cudaFuncSetAttribute(gemm_f16_v7<__half>,
                         cudaFuncAttributeMaxDynamicSharedMemorySize, GEMM_SMEM);
    cudaFuncSetAttribute(gemm_f16_v7<float>,
                         cudaFuncAttributeMaxDynamicSharedMemorySize, GEMM_SMEM);

    // 0) fused fp32 -> fp16 prepass (single launch)
    prepass_kernel<<<(N8_TOT + 255) / 256, 256>>>(x, qkv_w, proj_w);

    // 1) QKV GEMM: fp16 in / fp16 out
    {
        dim3 grid(THREEC / 128, MROWS / 256);   // (9, 392)
        gemm_f16_v7<__half><<<grid, 256, GEMM_SMEM>>>(xh_ptr, wqh_ptr, qkv_b,
                                                      qkvh_ptr, THREEC, CDIM);
    }
    // 2) windowed attention (tensor cores, fp16 in/out)
    {
        dim3 grid(BWIN, HHEADS);
        attn_mma<<<grid, 128>>>(mask);
    }
    // 3) Proj GEMM: fp16 in / fp32 out
    {
        dim3 grid(CDIM / 128, MROWS / 256);     // (3, 392)
        gemm_f16_v7<float><<<grid, 256, GEMM_SMEM>>>(atth_ptr, wph_ptr, proj_b,
                                                     out, CDIM, CDIM);
    }
}

// round 16
// speedup vs baseline: 1.1334x; 1.0109x over previous
#include <cuda_runtime.h>
#include <cuda_fp16.h>
#include <cstdint>

// Problem constants (fixed by reference)
#define BWIN   2048
#define NTOK   49
#define CDIM   384
#define HHEADS 12
#define DH     32
#define NWMASK 64
#define THREEC 1152
#define MROWS  (BWIN * NTOK)   // 100352

// Scratch (allocation-free rule: __device__ globals)
__device__ __half g_qkvh[(size_t)MROWS * THREEC];   // qkv, fp16
__device__ __half g_xh  [(size_t)MROWS * CDIM];     // x, fp16
__device__ __half g_atth[(size_t)MROWS * CDIM];     // attention out, fp16
__device__ __half g_wqh [(size_t)THREEC * CDIM];    // qkv_w, fp16
__device__ __half g_wph [(size_t)CDIM * CDIM];      // proj_w, fp16

// ---------------------------------------------------------------------------
// helpers
// ---------------------------------------------------------------------------
__device__ __forceinline__ void mma_f16_k16(float c[4],
                                            uint32_t a0, uint32_t a1, uint32_t a2, uint32_t a3,
                                            uint32_t b0, uint32_t b1) {
    asm volatile(
        "mma.sync.aligned.m16n8k16.row.col.f32.f16.f16.f32 "
        "{%0,%1,%2,%3}, {%4,%5,%6,%7}, {%8,%9}, {%0,%1,%2,%3};"
        : "+f"(c[0]), "+f"(c[1]), "+f"(c[2]), "+f"(c[3])
        : "r"(a0), "r"(a1), "r"(a2), "r"(a3), "r"(b0), "r"(b1));
}

__device__ __forceinline__ void mma_f16_k8(float c[4],
                                           uint32_t a0, uint32_t a1, uint32_t b0) {
    asm volatile(
        "mma.sync.aligned.m16n8k8.row.col.f32.f16.f16.f32 "
        "{%0,%1,%2,%3}, {%4,%5}, {%6}, {%0,%1,%2,%3};"
        : "+f"(c[0]), "+f"(c[1]), "+f"(c[2]), "+f"(c[3])
        : "r"(a0), "r"(a1), "r"(b0));
}

__device__ __forceinline__ void ldsm4(uint32_t& r0, uint32_t& r1,
                                      uint32_t& r2, uint32_t& r3, uint32_t addr) {
    asm volatile("ldmatrix.sync.aligned.m8n8.x4.shared.b16 {%0,%1,%2,%3}, [%4];"
                 : "=r"(r0), "=r"(r1), "=r"(r2), "=r"(r3) : "r"(addr));
}

__device__ __forceinline__ uint32_t smem_u32(const void* p) {
    return (uint32_t)__cvta_generic_to_shared(p);
}

// ---------------------------------------------------------------------------
// fused prepass: one launch converts x, qkv_w, proj_w (fp32 -> fp16, rn)
// ---------------------------------------------------------------------------
#define N8_X  ((MROWS * CDIM) / 8)      // 602112
#define N8_WQ ((THREEC * CDIM) / 8)     // 55296
#define N8_WP ((CDIM * CDIM) / 8)       // 18432
#define N8_TOT (N8_X + N8_WQ + N8_WP)

__global__ void prepass_kernel(const float* __restrict__ x,
                               const float* __restrict__ wq,
                               const float* __restrict__ wp)
{
    const int i = blockIdx.x * blockDim.x + threadIdx.x;
    if (i >= N8_TOT) return;

    const float* src;
    __half* dst;
    int j;
    if (i < N8_X)               { src = x;  dst = g_xh;  j = i; }
    else if (i < N8_X + N8_WQ)  { src = wq; dst = g_wqh; j = i - N8_X; }
    else                        { src = wp; dst = g_wph; j = i - N8_X - N8_WQ; }

    const float4 v0 = ((const float4*)src)[2 * j];
    const float4 v1 = ((const float4*)src)[2 * j + 1];
    __half2 h[4];
    h[0] = __floats2half2_rn(v0.x, v0.y);
    h[1] = __floats2half2_rn(v0.z, v0.w);
    h[2] = __floats2half2_rn(v1.x, v1.y);
    h[3] = __floats2half2_rn(v1.z, v1.w);
    ((uint4*)dst)[j] = *(uint4*)h;
}

// ---------------------------------------------------------------------------
// fp16 tensor-core GEMM v7b (R15 + bias staged in smem for the epilogue):
// CTA tile 256x128, 256 threads = 8 warps (4m x 2n), warp tile 64x64.
// Stage BK=64, two 32-wide producer phases, ONE __syncthreads per stage.
// ---------------------------------------------------------------------------
#define AWORDS 8192
#define BWORDS 4096
#define GEMM_SMEM ((AWORDS + BWORDS) * 2 * 4)   // 98304 (dynamic)

template <typename TO>
__global__ __launch_bounds__(256, 1) void gemm_f16_v7(
    const __half* __restrict__ A,
    const __half* __restrict__ W,
    const float* __restrict__ bias,
    TO* __restrict__ C,
    int Nout, int K)
{
    extern __shared__ __align__(16) uint32_t dsm[];
    uint32_t* const As = dsm;                     // [2][AWORDS]
    uint32_t* const Bs = dsm + 2 * AWORDS;        // [2][BWORDS]
    __shared__ float bsm[128];                    // bias tile (static, +512B)

    const int tid  = threadIdx.x;
    const int bm   = blockIdx.y * 256;
    const int bn   = blockIdx.x * 128;
    const int lane = tid & 31;
    const int warp = tid >> 5;
    const int warp_m = warp >> 1;
    const int warp_n = warp & 1;
    const int g = lane >> 2;
    const int t = lane & 3;

    const int ldr = tid >> 2;
    const int c   = tid & 3;
    const int kks0 = c >> 1;
    const int ph   = c & 1;

    const __half* Ab = A + (size_t)(bm + ldr) * K + c * 8;
    const __half* Wb = W + (size_t)(bn + ldr) * K + c * 8;

    if (tid < 128) bsm[tid] = bias[bn + tid];

    int aoff[2][4], boff[2][2];
#pragma unroll
    for (int p = 0; p < 2; ++p) {
        const int kks = kks0 + p * 2;
#pragma unroll
        for (int i = 0; i < 4; ++i) {
            const int row = ldr + i * 64;
            const int mi  = row >> 4;
            const int lr  = row & 15;
            aoff[p][i] = ((kks * 16 + mi) * 4 + ((lr >> 3) + 2 * ph)) * 32 + (lr & 7) * 4;
        }
#pragma unroll
        for (int i = 0; i < 2; ++i) {
            const int n = ldr + i * 64;
            boff[p][i] = ((kks * 16 + (n >> 3)) * 2 + ph) * 32 + (n & 7) * 4;
        }
    }

    uint4 ar[4], wr[2];

    auto load_ph = [&](int s, int p) {
        const int k0 = s * 64 + p * 32;
        ar[0] = *(const uint4*)(Ab + k0);
        ar[1] = *(const uint4*)(Ab + (size_t)64  * K + k0);
        ar[2] = *(const uint4*)(Ab + (size_t)128 * K + k0);
        ar[3] = *(const uint4*)(Ab + (size_t)192 * K + k0);
        wr[0] = *(const uint4*)(Wb + k0);
        wr[1] = *(const uint4*)(Wb + (size_t)64  * K + k0);
    };
    auto stash_ph = [&](int bf, int p) {
        uint32_t* Ad = As + bf * AWORDS;
        uint32_t* Bd = Bs + bf * BWORDS;
#pragma unroll
        for (int i = 0; i < 4; ++i) *(uint4*)&Ad[aoff[p][i]] = ar[i];
#pragma unroll
        for (int i = 0; i < 2; ++i) *(uint4*)&Bd[boff[p][i]] = wr[i];
    };

    float acc[4][8][4] = {};
    auto mma_step = [&](int bf, int kk) {
        uint32_t af[4][4], bfr[8][2];
        const uint32_t* Ap = As + bf * AWORDS + ((kk * 16 + warp_m * 4) * 4) * 32 + lane;
        const uint32_t* Bp = Bs + bf * BWORDS + ((kk * 16 + warp_n * 8) * 2) * 32 + lane;
#pragma unroll
        for (int mi = 0; mi < 4; ++mi)
#pragma unroll
            for (int r = 0; r < 4; ++r)
                af[mi][r] = Ap[(mi * 4 + r) * 32];
#pragma unroll
        for (int ni = 0; ni < 8; ++ni) {
            bfr[ni][0] = Bp[ni * 64];
            bfr[ni][1] = Bp[ni * 64 + 32];
        }
#pragma unroll
        for (int mi = 0; mi < 4; ++mi)
#pragma unroll
            for (int ni = 0; ni < 8; ++ni)
                mma_f16_k16(acc[mi][ni],
                            af[mi][0], af[mi][1], af[mi][2], af[mi][3],
                            bfr[ni][0], bfr[ni][1]);
    };

    load_ph(0, 0); stash_ph(0, 0);
    load_ph(0, 1); stash_ph(0, 1);
    __syncthreads();

    const int NS = K / 64;   // 6
    int buf = 0;
    for (int s = 0; s < NS; ++s) {
        const bool more = (s + 1 < NS);
        if (more) load_ph(s + 1, 0);
        mma_step(buf, 0);
        mma_step(buf, 1);
        if (more) { stash_ph(buf ^ 1, 0); load_ph(s + 1, 1); }
        mma_step(buf, 2);
        mma_step(buf, 3);
        if (more) {
            stash_ph(buf ^ 1, 1);
            __syncthreads();
            buf ^= 1;
        }
    }

#pragma unroll
    for (int mi = 0; mi < 4; ++mi) {
#pragma unroll
        for (int ni = 0; ni < 8; ++ni) {
            const int row  = bm + warp_m * 64 + mi * 16 + g;
            const int colL = warp_n * 64 + ni * 8 + 2 * t;
            const int col  = bn + colL;
            const float b0v = bsm[colL];
            const float b1v = bsm[colL + 1];
            const float v00 = acc[mi][ni][0] + b0v, v01 = acc[mi][ni][1] + b1v;
            const float v10 = acc[mi][ni][2] + b0v, v11 = acc[mi][ni][3] + b1v;
            if constexpr (sizeof(TO) == 2) {
                *(__half2*)((__half*)C + (size_t)row * Nout + col) =
                    __floats2half2_rn(v00, v01);
                *(__half2*)((__half*)C + (size_t)(row + 8) * Nout + col) =
                    __floats2half2_rn(v10, v11);
            } else {
                *(float2*)((float*)C + (size_t)row * Nout + col) = make_float2(v00, v01);
                *(float2*)((float*)C + (size_t)(row + 8) * Nout + col) = make_float2(v10, v11);
            }
        }
    }
}

// ---------------------------------------------------------------------------
// Tensor-core attention: one CTA (128 threads, 4 warps) per (window b, head h).
// R15 data path. vt zero-init narrowed to the only pad words PV can read:
// words 24..27 per row (halfs 48..55; PV's max j index is 55). Half 48 is
// valid data and is overwritten by the loader's 16-bit store AFTER the
// barrier; halfs 49..55 stay zero so P(=0) x pad never produces NaN. qh/kh
// garbage is safe (invalid-j scores unconditionally replaced by -1e30;
// invalid-i rows row-independent in softmax and store-guarded).
// ---------------------------------------------------------------------------
__global__ __launch_bounds__(128) void attn_mma(const float* __restrict__ mask)
{
    const int b = blockIdx.x;
    const int h = blockIdx.y;
    const int tid  = threadIdx.x;
    const int lane = tid & 31;
    const int w    = tid >> 5;
    const int g = lane >> 2;
    const int t = lane & 3;

    __shared__ __align__(16) __half qh[64][40];
    __shared__ __align__(16) __half kh[64][40];
    __shared__ __align__(16) __half vt[32][72];

    // zero the 4 pad words of each of the 32 rows (exactly 128 words),
    // then BARRIER before data stores (R14's lesson: no barrier -> race)
    {
        const int row = tid >> 2;          // 0..31
        const int wd  = 24 + (tid & 3);    // words 24..27 = halfs 48..55
        ((uint32_t*)vt[row])[wd] = 0;
    }
    __syncthreads();

    const __half* base = g_qkvh + (size_t)(b * NTOK) * THREEC + h * DH;
    for (int idx = tid; idx < NTOK * 16; idx += 128) {
        const int n  = idx >> 4;
        const int d2 = idx & 15;
        const uint32_t* p = (const uint32_t*)(base + (size_t)n * THREEC) + d2;
        const uint32_t q = p[0];
        const uint32_t k = p[CDIM / 2];
        const uint32_t v = p[CDIM];
        *(uint32_t*)&qh[n][d2 * 2] = q;
        *(uint32_t*)&kh[n][d2 * 2] = k;
        const __half2 vh = *(const __half2*)&v;
        vt[d2 * 2][n]     = __low2half(vh);
        vt[d2 * 2 + 1][n] = __high2half(vh);
    }
    __syncthreads();

    const int m0 = w * 16;
    const int r   = lane & 7;
    const int mat = lane >> 3;
    const int lrow = r + (mat & 1) * 8;
    const int lcol = (mat >> 1) * 8;

    uint32_t a[2][4];
#pragma unroll
    for (int s = 0; s < 2; ++s)
        ldsm4(a[s][0], a[s][1], a[s][2], a[s][3],
              smem_u32(&qh[m0 + lrow][lcol + s * 16]));

    float c[7][4] = {};
#pragma unroll
    for (int s = 0; s < 2; ++s) {
#pragma unroll
        for (int p = 0; p < 4; ++p) {
            uint32_t b0, b1, b2, b3;
            ldsm4(b0, b1, b2, b3, smem_u32(&kh[16 * p + lrow][lcol + s * 16]));
            mma_f16_k16(c[2 * p], a[s][0], a[s][1], a[s][2], a[s][3], b0, b2);
            if (2 * p + 1 < 7)
                mma_f16_k16(c[2 * p + 1], a[s][0], a[s][1], a[s][2], a[s][3], b1, b3);
        }
    }

    const float scale = 0.17677669529663687f;
    const float* mrow = mask + (size_t)(b & (NWMASK - 1)) * NTOK * NTOK;
    const int i1 = m0 + g;
    const int i2 = m0 + 8 + g;
    const int mi1 = (i1 < NTOK) ? i1 : NTOK - 1;
    const int mi2 = (i2 < NTOK) ? i2 : NTOK - 1;
#pragma unroll
    for (int nt = 0; nt < 7; ++nt) {
        const int j0 = nt * 8 + 2 * t;
        c[nt][0] = (j0     < NTOK) ? c[nt][0] * scale + __ldg(mrow + mi1 * NTOK + j0)     : -1e30f;
        c[nt][1] = (j0 + 1 < NTOK) ? c[nt][1] * scale + __ldg(mrow + mi1 * NTOK + j0 + 1) : -1e30f;
        c[nt][2] = (j0     < NTOK) ? c[nt][2] * scale + __ldg(mrow + mi2 * NTOK + j0)     : -1e30f;
        c[nt][3] = (j0 + 1 < NTOK) ? c[nt][3] * scale + __ldg(mrow + mi2 * NTOK + j0 + 1) : -1e30f;
    }

    float mx1 = -1e30f, mx2 = -1e30f;
#pragma unroll
    for (int nt = 0; nt < 7; ++nt) {
        mx1 = fmaxf(mx1, fmaxf(c[nt][0], c[nt][1]));
        mx2 = fmaxf(mx2, fmaxf(c[nt][2], c[nt][3]));
    }
    mx1 = fmaxf(mx1, __shfl_xor_sync(0xffffffffu, mx1, 1));
    mx1 = fmaxf(mx1, __shfl_xor_sync(0xffffffffu, mx1, 2));
    mx2 = fmaxf(mx2, __shfl_xor_sync(0xffffffffu, mx2, 1));
    mx2 = fmaxf(mx2, __shfl_xor_sync(0xffffffffu, mx2, 2));

    float s1 = 0.f, s2 = 0.f;
#pragma unroll
    for (int nt = 0; nt < 7; ++nt) {
        c[nt][0] = __expf(c[nt][0] - mx1);
        c[nt][1] = __expf(c[nt][1] - mx1);
        c[nt][2] = __expf(c[nt][2] - mx2);
        c[nt][3] = __expf(c[nt][3] - mx2);
        s1 += c[nt][0] + c[nt][1];
        s2 += c[nt][2] + c[nt][3];
    }
    s1 += __shfl_xor_sync(0xffffffffu, s1, 1);
    s1 += __shfl_xor_sync(0xffffffffu, s1, 2);
    s2 += __shfl_xor_sync(0xffffffffu, s2, 1);
    s2 += __shfl_xor_sync(0xffffffffu, s2, 2);
    const float inv1 = 1.0f / s1;
    const float inv2 = 1.0f / s2;

    uint32_t pa[7][2];
#pragma unroll
    for (int nt = 0; nt < 7; ++nt) {
        const __half2 p0 = __floats2half2_rn(c[nt][0] * inv1, c[nt][1] * inv1);
        const __half2 p1 = __floats2half2_rn(c[nt][2] * inv2, c[nt][3] * inv2);
        pa[nt][0] = *(const uint32_t*)&p0;
        pa[nt][1] = *(const uint32_t*)&p1;
    }

    float o[4][4] = {};
#pragma unroll
    for (int kc = 0; kc < 7; ++kc) {
#pragma unroll
        for (int dt = 0; dt < 4; ++dt) {
            const uint32_t bv = *(const uint32_t*)&vt[dt * 8 + g][kc * 8 + 2 * t];
            mma_f16_k8(o[dt], pa[kc][0], pa[kc][1], bv);
        }
    }

    __half* ob = g_atth + (size_t)(b * NTOK) * CDIM + h * DH;
#pragma unroll
    for (int dt = 0; dt < 4; ++dt) {
        const int d0 = dt * 8 + 2 * t;
        if (i1 < NTOK)
            *(__half2*)(ob + (size_t)i1 * CDIM + d0) = __floats2half2_rn(o[dt][0], o[dt][1]);
        if (i2 < NTOK)
            *(__half2*)(ob + (size_t)i2 * CDIM + d0) = __floats2half2_rn(o[dt][2], o[dt][3]);
    }
}

// ---------------------------------------------------------------------------
// launch
// ---------------------------------------------------------------------------
extern "C" void kernel_launch(void* const* d_in, const int* in_sizes, int n_in,
                              void* d_out, int out_size)
{
    const float* x      = (const float*)d_in[0];
    const float* mask   = (const float*)d_in[1];
    const float* qkv_w  = (const float*)d_in[2];
    const float* qkv_b  = (const float*)d_in[3];
    const float* proj_w = (const float*)d_in[4];
    const float* proj_b = (const float*)d_in[5];
    float* out = (float*)d_out;

    __half *qkvh_ptr, *xh_ptr, *atth_ptr, *wqh_ptr, *wph_ptr;
    cudaGetSymbolAddress((void**)&qkvh_ptr, g_qkvh);
    cudaGetSymbolAddress((void**)&xh_ptr,   g_xh);
    cudaGetSymbolAddress((void**)&atth_ptr, g_atth);
    cudaGetSymbolAddress((void**)&wqh_ptr,  g_wqh);
    cudaGetSymbolAddress((void**)&wph_ptr,  g_wph);

    cudaFuncSetAttribute(gemm_f16_v7<__half>,
                         cudaFuncAttributeMaxDynamicSharedMemorySize, GEMM_SMEM);
    cudaFuncSetAttribute(gemm_f16_v7<float>,
                         cudaFuncAttributeMaxDynamicSharedMemorySize, GEMM_SMEM);

    // 0) fused fp32 -> fp16 prepass (single launch)
    prepass_kernel<<<(N8_TOT + 255) / 256, 256>>>(x, qkv_w, proj_w);

    // 1) QKV GEMM: fp16 in / fp16 out
    {
        dim3 grid(THREEC / 128, MROWS / 256);   // (9, 392)
        gemm_f16_v7<__half><<<grid, 256, GEMM_SMEM>>>(xh_ptr, wqh_ptr, qkv_b,
                                                      qkvh_ptr, THREEC, CDIM);
    }
    // 2) windowed attention (tensor cores, fp16 in/out)
    {
        dim3 grid(BWIN, HHEADS);
        attn_mma<<<grid, 128>>>(mask);
    }
    // 3) Proj GEMM: fp16 in / fp32 out
    {
        dim3 grid(CDIM / 128, MROWS / 256);     // (3, 392)
        gemm_f16_v7<float><<<grid, 256, GEMM_SMEM>>>(atth_ptr, wph_ptr, proj_b,
                                                     out, CDIM, CDIM);
    }
}

// round 17
// speedup vs baseline: 1.1426x; 1.0082x over previous
#include <cuda_runtime.h>
#include <cuda_fp16.h>
#include <cstdint>

// Problem constants (fixed by reference)
#define BWIN   2048
#define NTOK   49
#define CDIM   384
#define HHEADS 12
#define DH     32
#define NWMASK 64
#define THREEC 1152
#define MROWS  (BWIN * NTOK)   // 100352

// Scratch (allocation-free rule: __device__ globals)
__device__ __half g_qkvh[(size_t)MROWS * THREEC];   // qkv, fp16
__device__ __half g_xh  [(size_t)MROWS * CDIM];     // x, fp16
__device__ __half g_atth[(size_t)MROWS * CDIM];     // attention out, fp16
__device__ __half g_wqh [(size_t)THREEC * CDIM];    // qkv_w, fp16
__device__ __half g_wph [(size_t)CDIM * CDIM];      // proj_w, fp16

// ---------------------------------------------------------------------------
// helpers
// ---------------------------------------------------------------------------
__device__ __forceinline__ void mma_f16_k16(float c[4],
                                            uint32_t a0, uint32_t a1, uint32_t a2, uint32_t a3,
                                            uint32_t b0, uint32_t b1) {
    asm volatile(
        "mma.sync.aligned.m16n8k16.row.col.f32.f16.f16.f32 "
        "{%0,%1,%2,%3}, {%4,%5,%6,%7}, {%8,%9}, {%0,%1,%2,%3};"
        : "+f"(c[0]), "+f"(c[1]), "+f"(c[2]), "+f"(c[3])
        : "r"(a0), "r"(a1), "r"(a2), "r"(a3), "r"(b0), "r"(b1));
}

__device__ __forceinline__ void mma_f16_k8(float c[4],
                                           uint32_t a0, uint32_t a1, uint32_t b0) {
    asm volatile(
        "mma.sync.aligned.m16n8k8.row.col.f32.f16.f16.f32 "
        "{%0,%1,%2,%3}, {%4,%5}, {%6}, {%0,%1,%2,%3};"
        : "+f"(c[0]), "+f"(c[1]), "+f"(c[2]), "+f"(c[3])
        : "r"(a0), "r"(a1), "r"(b0));
}

__device__ __forceinline__ void ldsm4(uint32_t& r0, uint32_t& r1,
                                      uint32_t& r2, uint32_t& r3, uint32_t addr) {
    asm volatile("ldmatrix.sync.aligned.m8n8.x4.shared.b16 {%0,%1,%2,%3}, [%4];"
                 : "=r"(r0), "=r"(r1), "=r"(r2), "=r"(r3) : "r"(addr));
}

__device__ __forceinline__ uint32_t smem_u32(const void* p) {
    return (uint32_t)__cvta_generic_to_shared(p);
}

// ---------------------------------------------------------------------------
// fused prepass: one launch converts x, qkv_w, proj_w (fp32 -> fp16, rn)
// ---------------------------------------------------------------------------
#define N8_X  ((MROWS * CDIM) / 8)      // 602112
#define N8_WQ ((THREEC * CDIM) / 8)     // 55296
#define N8_WP ((CDIM * CDIM) / 8)       // 18432
#define N8_TOT (N8_X + N8_WQ + N8_WP)

__global__ void prepass_kernel(const float* __restrict__ x,
                               const float* __restrict__ wq,
                               const float* __restrict__ wp)
{
    const int i = blockIdx.x * blockDim.x + threadIdx.x;
    if (i >= N8_TOT) return;

    const float* src;
    __half* dst;
    int j;
    if (i < N8_X)               { src = x;  dst = g_xh;  j = i; }
    else if (i < N8_X + N8_WQ)  { src = wq; dst = g_wqh; j = i - N8_X; }
    else                        { src = wp; dst = g_wph; j = i - N8_X - N8_WQ; }

    const float4 v0 = ((const float4*)src)[2 * j];
    const float4 v1 = ((const float4*)src)[2 * j + 1];
    __half2 h[4];
    h[0] = __floats2half2_rn(v0.x, v0.y);
    h[1] = __floats2half2_rn(v0.z, v0.w);
    h[2] = __floats2half2_rn(v1.x, v1.y);
    h[3] = __floats2half2_rn(v1.z, v1.w);
    ((uint4*)dst)[j] = *(uint4*)h;
}

// ---------------------------------------------------------------------------
// fp16 tensor-core GEMM v7b (R16 verbatim — proven 424 us QKV / 147 us proj):
// CTA tile 256x128, 256 threads = 8 warps (4m x 2n), warp tile 64x64.
// Stage BK=64, two 32-wide producer phases, ONE __syncthreads per stage.
// Bias staged in smem for the epilogue.
// ---------------------------------------------------------------------------
#define AWORDS 8192
#define BWORDS 4096
#define GEMM_SMEM ((AWORDS + BWORDS) * 2 * 4)   // 98304 (dynamic)

template <typename TO>
__global__ __launch_bounds__(256, 1) void gemm_f16_v7(
    const __half* __restrict__ A,
    const __half* __restrict__ W,
    const float* __restrict__ bias,
    TO* __restrict__ C,
    int Nout, int K)
{
    extern __shared__ __align__(16) uint32_t dsm[];
    uint32_t* const As = dsm;                     // [2][AWORDS]
    uint32_t* const Bs = dsm + 2 * AWORDS;        // [2][BWORDS]
    __shared__ float bsm[128];

    const int tid  = threadIdx.x;
    const int bm   = blockIdx.y * 256;
    const int bn   = blockIdx.x * 128;
    const int lane = tid & 31;
    const int warp = tid >> 5;
    const int warp_m = warp >> 1;
    const int warp_n = warp & 1;
    const int g = lane >> 2;
    const int t = lane & 3;

    const int ldr = tid >> 2;
    const int c   = tid & 3;
    const int kks0 = c >> 1;
    const int ph   = c & 1;

    const __half* Ab = A + (size_t)(bm + ldr) * K + c * 8;
    const __half* Wb = W + (size_t)(bn + ldr) * K + c * 8;

    if (tid < 128) bsm[tid] = bias[bn + tid];

    int aoff[2][4], boff[2][2];
#pragma unroll
    for (int p = 0; p < 2; ++p) {
        const int kks = kks0 + p * 2;
#pragma unroll
        for (int i = 0; i < 4; ++i) {
            const int row = ldr + i * 64;
            const int mi  = row >> 4;
            const int lr  = row & 15;
            aoff[p][i] = ((kks * 16 + mi) * 4 + ((lr >> 3) + 2 * ph)) * 32 + (lr & 7) * 4;
        }
#pragma unroll
        for (int i = 0; i < 2; ++i) {
            const int n = ldr + i * 64;
            boff[p][i] = ((kks * 16 + (n >> 3)) * 2 + ph) * 32 + (n & 7) * 4;
        }
    }

    uint4 ar[4], wr[2];

    auto load_ph = [&](int s, int p) {
        const int k0 = s * 64 + p * 32;
        ar[0] = *(const uint4*)(Ab + k0);
        ar[1] = *(const uint4*)(Ab + (size_t)64  * K + k0);
        ar[2] = *(const uint4*)(Ab + (size_t)128 * K + k0);
        ar[3] = *(const uint4*)(Ab + (size_t)192 * K + k0);
        wr[0] = *(const uint4*)(Wb + k0);
        wr[1] = *(const uint4*)(Wb + (size_t)64  * K + k0);
    };
    auto stash_ph = [&](int bf, int p) {
        uint32_t* Ad = As + bf * AWORDS;
        uint32_t* Bd = Bs + bf * BWORDS;
#pragma unroll
        for (int i = 0; i < 4; ++i) *(uint4*)&Ad[aoff[p][i]] = ar[i];
#pragma unroll
        for (int i = 0; i < 2; ++i) *(uint4*)&Bd[boff[p][i]] = wr[i];
    };

    float acc[4][8][4] = {};
    auto mma_step = [&](int bf, int kk) {
        uint32_t af[4][4], bfr[8][2];
        const uint32_t* Ap = As + bf * AWORDS + ((kk * 16 + warp_m * 4) * 4) * 32 + lane;
        const uint32_t* Bp = Bs + bf * BWORDS + ((kk * 16 + warp_n * 8) * 2) * 32 + lane;
#pragma unroll
        for (int mi = 0; mi < 4; ++mi)
#pragma unroll
            for (int r = 0; r < 4; ++r)
                af[mi][r] = Ap[(mi * 4 + r) * 32];
#pragma unroll
        for (int ni = 0; ni < 8; ++ni) {
            bfr[ni][0] = Bp[ni * 64];
            bfr[ni][1] = Bp[ni * 64 + 32];
        }
#pragma unroll
        for (int mi = 0; mi < 4; ++mi)
#pragma unroll
            for (int ni = 0; ni < 8; ++ni)
                mma_f16_k16(acc[mi][ni],
                            af[mi][0], af[mi][1], af[mi][2], af[mi][3],
                            bfr[ni][0], bfr[ni][1]);
    };

    load_ph(0, 0); stash_ph(0, 0);
    load_ph(0, 1); stash_ph(0, 1);
    __syncthreads();

    const int NS = K / 64;   // 6
    int buf = 0;
    for (int s = 0; s < NS; ++s) {
        const bool more = (s + 1 < NS);
        if (more) load_ph(s + 1, 0);
        mma_step(buf, 0);
        mma_step(buf, 1);
        if (more) { stash_ph(buf ^ 1, 0); load_ph(s + 1, 1); }
        mma_step(buf, 2);
        mma_step(buf, 3);
        if (more) {
            stash_ph(buf ^ 1, 1);
            __syncthreads();
            buf ^= 1;
        }
    }

#pragma unroll
    for (int mi = 0; mi < 4; ++mi) {
#pragma unroll
        for (int ni = 0; ni < 8; ++ni) {
            const int row  = bm + warp_m * 64 + mi * 16 + g;
            const int colL = warp_n * 64 + ni * 8 + 2 * t;
            const int col  = bn + colL;
            const float b0v = bsm[colL];
            const float b1v = bsm[colL + 1];
            const float v00 = acc[mi][ni][0] + b0v, v01 = acc[mi][ni][1] + b1v;
            const float v10 = acc[mi][ni][2] + b0v, v11 = acc[mi][ni][3] + b1v;
            if constexpr (sizeof(TO) == 2) {
                *(__half2*)((__half*)C + (size_t)row * Nout + col) =
                    __floats2half2_rn(v00, v01);
                *(__half2*)((__half*)C + (size_t)(row + 8) * Nout + col) =
                    __floats2half2_rn(v10, v11);
            } else {
                *(float2*)((float*)C + (size_t)row * Nout + col) = make_float2(v00, v01);
                *(float2*)((float*)C + (size_t)(row + 8) * Nout + col) = make_float2(v10, v11);
            }
        }
    }
}

// ---------------------------------------------------------------------------
// Tensor-core attention: one CTA (128 threads, 4 warps) per (window b, head h).
// R16 data path + VECTORIZED loader: uint4 (16B) q/k/v loads over 49 rows x
// 4 d8-groups (196 items), single STS.128 into qh/kh (16B-aligned: row
// stride 80B, offsets d8*16). Cuts loader LDG 2352->588 and qh/kh STS
// 1568->392 per CTA. vt transpose scatter unchanged (scalar 2B stores).
// vt pad words 24..27/row zeroed + barrier (R14 lesson).
// ---------------------------------------------------------------------------
__global__ __launch_bounds__(128) void attn_mma(const float* __restrict__ mask)
{
    const int b = blockIdx.x;
    const int h = blockIdx.y;
    const int tid  = threadIdx.x;
    const int lane = tid & 31;
    const int w    = tid >> 5;
    const int g = lane >> 2;
    const int t = lane & 3;

    __shared__ __align__(16) __half qh[64][40];
    __shared__ __align__(16) __half kh[64][40];
    __shared__ __align__(16) __half vt[32][72];

    // zero the 4 pad words of each of the 32 vt rows (exactly 128 words),
    // then BARRIER before data stores
    {
        const int row = tid >> 2;          // 0..31
        const int wd  = 24 + (tid & 3);    // words 24..27 = halfs 48..55
        ((uint32_t*)vt[row])[wd] = 0;
    }
    __syncthreads();

    // vectorized q/k/v stage: 196 uint4-items (49 rows x 4 d8-groups)
    const __half* base = g_qkvh + (size_t)(b * NTOK) * THREEC + h * DH;
    for (int idx = tid; idx < NTOK * 4; idx += 128) {
        const int n  = idx >> 2;           // 0..48
        const int d8 = idx & 3;            // 0..3 (halfs d8*8 .. d8*8+7)
        const __half* rp = base + (size_t)n * THREEC + d8 * 8;
        const uint4 q = *(const uint4*)(rp);
        const uint4 k = *(const uint4*)(rp + CDIM);
        const uint4 v = *(const uint4*)(rp + 2 * CDIM);
        *(uint4*)&qh[n][d8 * 8] = q;
        *(uint4*)&kh[n][d8 * 8] = k;
        // transpose V: 8 halfs -> vt[d8*8 + i][n]
        const __half2* vh = (const __half2*)&v;
#pragma unroll
        for (int i = 0; i < 4; ++i) {
            vt[d8 * 8 + 2 * i][n]     = __low2half(vh[i]);
            vt[d8 * 8 + 2 * i + 1][n] = __high2half(vh[i]);
        }
    }
    __syncthreads();

    const int m0 = w * 16;
    const int r   = lane & 7;
    const int mat = lane >> 3;
    const int lrow = r + (mat & 1) * 8;
    const int lcol = (mat >> 1) * 8;

    uint32_t a[2][4];
#pragma unroll
    for (int s = 0; s < 2; ++s)
        ldsm4(a[s][0], a[s][1], a[s][2], a[s][3],
              smem_u32(&qh[m0 + lrow][lcol + s * 16]));

    float c[7][4] = {};
#pragma unroll
    for (int s = 0; s < 2; ++s) {
#pragma unroll
        for (int p = 0; p < 4; ++p) {
            uint32_t b0, b1, b2, b3;
            ldsm4(b0, b1, b2, b3, smem_u32(&kh[16 * p + lrow][lcol + s * 16]));
            mma_f16_k16(c[2 * p], a[s][0], a[s][1], a[s][2], a[s][3], b0, b2);
            if (2 * p + 1 < 7)
                mma_f16_k16(c[2 * p + 1], a[s][0], a[s][1], a[s][2], a[s][3], b1, b3);
        }
    }

    const float scale = 0.17677669529663687f;
    const float* mrow = mask + (size_t)(b & (NWMASK - 1)) * NTOK * NTOK;
    const int i1 = m0 + g;
    const int i2 = m0 + 8 + g;
    const int mi1 = (i1 < NTOK) ? i1 : NTOK - 1;
    const int mi2 = (i2 < NTOK) ? i2 : NTOK - 1;
#pragma unroll
    for (int nt = 0; nt < 7; ++nt) {
        const int j0 = nt * 8 + 2 * t;
        c[nt][0] = (j0     < NTOK) ? c[nt][0] * scale + __ldg(mrow + mi1 * NTOK + j0)     : -1e30f;
        c[nt][1] = (j0 + 1 < NTOK) ? c[nt][1] * scale + __ldg(mrow + mi1 * NTOK + j0 + 1) : -1e30f;
        c[nt][2] = (j0     < NTOK) ? c[nt][2] * scale + __ldg(mrow + mi2 * NTOK + j0)     : -1e30f;
        c[nt][3] = (j0 + 1 < NTOK) ? c[nt][3] * scale + __ldg(mrow + mi2 * NTOK + j0 + 1) : -1e30f;
    }

    float mx1 = -1e30f, mx2 = -1e30f;
#pragma unroll
    for (int nt = 0; nt < 7; ++nt) {
        mx1 = fmaxf(mx1, fmaxf(c[nt][0], c[nt][1]));
        mx2 = fmaxf(mx2, fmaxf(c[nt][2], c[nt][3]));
    }
    mx1 = fmaxf(mx1, __shfl_xor_sync(0xffffffffu, mx1, 1));
    mx1 = fmaxf(mx1, __shfl_xor_sync(0xffffffffu, mx1, 2));
    mx2 = fmaxf(mx2, __shfl_xor_sync(0xffffffffu, mx2, 1));
    mx2 = fmaxf(mx2, __shfl_xor_sync(0xffffffffu, mx2, 2));

    float s1 = 0.f, s2 = 0.f;
#pragma unroll
    for (int nt = 0; nt < 7; ++nt) {
        c[nt][0] = __expf(c[nt][0] - mx1);
        c[nt][1] = __expf(c[nt][1] - mx1);
        c[nt][2] = __expf(c[nt][2] - mx2);
        c[nt][3] = __expf(c[nt][3] - mx2);
        s1 += c[nt][0] + c[nt][1];
        s2 += c[nt][2] + c[nt][3];
    }
    s1 += __shfl_xor_sync(0xffffffffu, s1, 1);
    s1 += __shfl_xor_sync(0xffffffffu, s1, 2);
    s2 += __shfl_xor_sync(0xffffffffu, s2, 1);
    s2 += __shfl_xor_sync(0xffffffffu, s2, 2);
    const float inv1 = 1.0f / s1;
    const float inv2 = 1.0f / s2;

    uint32_t pa[7][2];
#pragma unroll
    for (int nt = 0; nt < 7; ++nt) {
        const __half2 p0 = __floats2half2_rn(c[nt][0] * inv1, c[nt][1] * inv1);
        const __half2 p1 = __floats2half2_rn(c[nt][2] * inv2, c[nt][3] * inv2);
        pa[nt][0] = *(const uint32_t*)&p0;
        pa[nt][1] = *(const uint32_t*)&p1;
    }

    float o[4][4] = {};
#pragma unroll
    for (int kc = 0; kc < 7; ++kc) {
#pragma unroll
        for (int dt = 0; dt < 4; ++dt) {
            const uint32_t bv = *(const uint32_t*)&vt[dt * 8 + g][kc * 8 + 2 * t];
            mma_f16_k8(o[dt], pa[kc][0], pa[kc][1], bv);
        }
    }

    __half* ob = g_atth + (size_t)(b * NTOK) * CDIM + h * DH;
#pragma unroll
    for (int dt = 0; dt < 4; ++dt) {
        const int d0 = dt * 8 + 2 * t;
        if (i1 < NTOK)
            *(__half2*)(ob + (size_t)i1 * CDIM + d0) = __floats2half2_rn(o[dt][0], o[dt][1]);
        if (i2 < NTOK)
            *(__half2*)(ob + (size_t)i2 * CDIM + d0) = __floats2half2_rn(o[dt][2], o[dt][3]);
    }
}

// ---------------------------------------------------------------------------
// launch
// ---------------------------------------------------------------------------
extern "C" void kernel_launch(void* const* d_in, const int* in_sizes, int n_in,
                              void* d_out, int out_size)
{
    const float* x      = (const float*)d_in[0];
    const float* mask   = (const float*)d_in[1];
    const float* qkv_w  = (const float*)d_in[2];
    const float* qkv_b  = (const float*)d_in[3];
    const float* proj_w = (const float*)d_in[4];
    const float* proj_b = (const float*)d_in[5];
    float* out = (float*)d_out;

    __half *qkvh_ptr, *xh_ptr, *atth_ptr, *wqh_ptr, *wph_ptr;
    cudaGetSymbolAddress((void**)&qkvh_ptr, g_qkvh);
    cudaGetSymbolAddress((void**)&xh_ptr,   g_xh);
    cudaGetSymbolAddress((void**)&atth_ptr, g_atth);
    cudaGetSymbolAddress((void**)&wqh_ptr,  g_wqh);
    cudaGetSymbolAddress((void**)&wph_ptr,  g_wph);

    cudaFuncSetAttribute(gemm_f16_v7<__half>,
                         cudaFuncAttributeMaxDynamicSharedMemorySize, GEMM_SMEM);
    cudaFuncSetAttribute(gemm_f16_v7<float>,
                         cudaFuncAttributeMaxDynamicSharedMemorySize, GEMM_SMEM);

    // 0) fused fp32 -> fp16 prepass (single launch)
    prepass_kernel<<<(N8_TOT + 255) / 256, 256>>>(x, qkv_w, proj_w);

    // 1) QKV GEMM: fp16 in / fp16 out
    {
        dim3 grid(THREEC / 128, MROWS / 256);   // (9, 392)
        gemm_f16_v7<__half><<<grid, 256, GEMM_SMEM>>>(xh_ptr, wqh_ptr, qkv_b,
                                                      qkvh_ptr, THREEC, CDIM);
    }
    // 2) windowed attention (tensor cores, fp16 in/out)
    {
        dim3 grid(BWIN, HHEADS);
        attn_mma<<<grid, 128>>>(mask);
    }
    // 3) Proj GEMM: fp16 in / fp32 out
    {
        dim3 grid(CDIM / 128, MROWS / 256);     // (3, 392)
        gemm_f16_v7<float><<<grid, 256, GEMM_SMEM>>>(atth_ptr, wph_ptr, proj_b,
                                                     out, CDIM, CDIM);
    }
}